// round 16
// baseline (speedup 1.0000x reference)
#include <cuda_runtime.h>
#include <cstdint>

// ---------------------------------------------------------------------------
// CompositionalLoss via tree prefix sums (scalar, FFMA-imm edition).
//   a[j] = a[par(j)] + b[j]   (a[root]=0)
//   e[j] = a[j] - t[j],  f[j] = e[j] - b[j]
//   delta(u,v) = e[u] - f[v] - b[lca];  lca==v -> e[u]-e[v]; lca==u -> f[u]-f[v]
//   Only branching nodes are Hip(3) and Chest(1) -> cross LCA is 1 or 3.
// Key uarch facts used (B300 measured):
//   FFMA R,R,IMM,R has rt_SMSP=1 (2x the throughput of FADD rt=2)
//     -> ALL adds/subs expressed as fma(x, +-1.0f, y)  (exact arithmetic)
//   |x| done as integer AND (LOP3) on the alu pipe, off the fma pipe.
// Geometry: 96-thread blocks (3 warps = 3 channels x 32 samples), SPB=32,
//   16.1KB smem -> 12 resident blocks/SM (reg-bound at 56) = 56% occupancy.
// ---------------------------------------------------------------------------

#define NJ 21
#define NPAIRS 210
#define SPB 32
#define THREADS 96
#define MAXBLOCKS 4096
#define TILE_FLOATS (SPB * 63)          // 2016 per array

__device__ float g_partials[MAXBLOCKS];
__device__ unsigned int g_count = 0;    // self-resets each launch (graph-safe)

// Kinematic tree (JOINTS alphabetical): parent index per joint.
__host__ __device__ constexpr int par(int j) {
    switch (j) {
        case 0:  return 3;   case 1:  return 0;   case 2:  return 12;
        case 3:  return 3;   case 4:  return 11;  case 5:  return 7;
        case 6:  return 4;   case 7:  return 9;   case 8:  return 1;
        case 9:  return 3;   case 10: return 5;   case 11: return 8;
        case 12: return 1;   case 13: return 20;  case 14: return 16;
        case 15: return 13;  case 16: return 18;  case 17: return 1;
        case 18: return 3;   case 19: return 14;  default: return 17;
    }
}
__host__ __device__ constexpr int depthf(int j) {
    int d = 0;
    while (par(j) != j) { j = par(j); ++d; }
    return d;
}
__host__ __device__ constexpr int lcaf(int u, int v) {
    int du = depthf(u), dv = depthf(v);
    while (du > dv) { u = par(u); --du; }
    while (dv > du) { v = par(v); --dv; }
    while (u != v) { u = par(u); v = par(v); }
    return u;
}
// Pair enumeration sorted by v (CSE of per-v group terms, short live ranges).
__host__ __device__ constexpr int qv(int q) {
    int v = 1;
    while (v * (v + 1) / 2 <= q) ++v;
    return v;
}
__host__ __device__ constexpr int qu(int q) {
    int v = qv(q);
    return q - v * (v - 1) / 2;
}

// ---- FFMA-imm primitives: rt_SMSP=1 (vs FADD rt=2). All exact. ----
__device__ __forceinline__ float addi(float a, float b) {   // a + b
    return __fmaf_rn(a, 1.0f, b);
}
__device__ __forceinline__ float subi(float a, float b) {   // a - b
    return __fmaf_rn(b, -1.0f, a);
}
__device__ __forceinline__ float absf_alu(float x) {        // LOP3 on alu pipe
    return __int_as_float(__float_as_int(x) & 0x7fffffff);
}

// Fully-unrolled pair accumulation with compile-time indices; 4 acc chains.
template <int P, int N>
struct PairRun {
    static __device__ __forceinline__ void run(const float (&e)[NJ], const float (&f)[NJ],
                                               float b1, float b3, float (&acc)[4]) {
        PairRun<P, N / 2>::run(e, f, b1, b3, acc);
        PairRun<P + N / 2, N - N / 2>::run(e, f, b1, b3, acc);
    }
};
template <int P>
struct PairRun<P, 1> {
    static __device__ __forceinline__ void run(const float (&e)[NJ], const float (&f)[NJ],
                                               float b1, float b3, float (&acc)[4]) {
        constexpr int u = qu(P);
        constexpr int v = qv(P);
        constexpr int w = lcaf(u, v);
        static_assert(w == u || w == v || w == 1 || w == 3, "unexpected LCA");
        float d;
        if constexpr (w == v)       d = subi(e[u], e[v]);
        else if constexpr (w == u)  d = subi(f[u], f[v]);
        else if constexpr (w == 1)  d = subi(e[u], addi(f[v], b1));  // CSE per v
        else                        d = subi(e[u], addi(f[v], b3));  // CSE per v
        acc[P & 3] = addi(acc[P & 3], absf_alu(d));   // FFMA-imm + LOP3
    }
};

__device__ __forceinline__ uint32_t smem_u32(const void* p) {
    return (uint32_t)__cvta_generic_to_shared(p);
}
__device__ __forceinline__ void cp_async16(uint32_t dst, const void* src) {
    asm volatile("cp.async.cg.shared.global [%0], [%1], 16;" :: "r"(dst), "l"(src));
}

__global__ __launch_bounds__(THREADS, 12)
void comploss_kernel(const float* __restrict__ gin, const float* __restrict__ gtg,
                     float* __restrict__ out, int B, float invB, int nblocks) {
    __shared__ __align__(16) float sIn[TILE_FLOATS];
    __shared__ __align__(16) float sTg[TILE_FLOATS];
    __shared__ float sRed[THREADS / 32];
    __shared__ bool sLast;

    const int tid = threadIdx.x;
    const long long s0 = (long long)blockIdx.x * SPB;
    int nsamp = B - (int)s0;
    if (nsamp > SPB) nsamp = SPB;

    // ---- stage gmem -> smem via cp.async ----
    if (nsamp == SPB) {
        const float4* gi = reinterpret_cast<const float4*>(gin + s0 * 63);
        const float4* gt = reinterpret_cast<const float4*>(gtg + s0 * 63);
        const uint32_t si = smem_u32(sIn);
        const uint32_t st = smem_u32(sTg);
        for (int i = tid; i < TILE_FLOATS / 4; i += THREADS) {
            cp_async16(si + i * 16, gi + i);
            cp_async16(st + i * 16, gt + i);
        }
        asm volatile("cp.async.commit_group;");
        asm volatile("cp.async.wait_group 0;" ::: "memory");
    } else {
        for (int i = tid; i < TILE_FLOATS; i += THREADS) {
            bool ok = i < nsamp * 63;
            sIn[i] = ok ? gin[s0 * 63 + i] : 0.0f;   // zero-pad: contributes 0
            sTg[i] = ok ? gtg[s0 * 63 + i] : 0.0f;
        }
    }
    __syncthreads();

    // ---- per-(sample,channel) compute ----
    const int c = tid >> 5;        // channel 0..2, uniform per warp
    const int s = tid & 31;        // sample in tile; stride-63 smem: conflict-free
    const float* bp = sIn + s * 63 + c;
    const float* tp = sTg + s * 63 + c;

    float e[NJ], f[NJ], a[NJ];
    float b1, b3;
    // Streaming loads: b,t consumed at point of use; only e/f/b1/b3 stay live.
#define LOADJ(j, apar)                                    \
    { float bb = bp[3 * (j)]; float tt = tp[3 * (j)];     \
      a[j] = addi(apar, bb);                              \
      e[j] = subi(a[j], tt);                              \
      f[j] = subi(e[j], bb); }

    { float bb = bp[9]; float tt = tp[9];                 // root Hip=3, a=0
      a[3] = 0.0f;
      e[3] = subi(0.0f, tt);
      f[3] = subi(e[3], bb);
      b3 = bb; }
    LOADJ(0,  a[3]);
    { float bb = bp[3]; float tt = tp[3];                 // Chest=1, keep b1
      a[1] = addi(a[0], bb);
      e[1] = subi(a[1], tt);
      f[1] = subi(e[1], bb);
      b1 = bb; }
    LOADJ(8,  a[1]);
    LOADJ(12, a[1]);
    LOADJ(17, a[1]);
    LOADJ(2,  a[12]);
    LOADJ(9,  a[3]);
    LOADJ(18, a[3]);
    LOADJ(11, a[8]);
    LOADJ(20, a[17]);
    LOADJ(7,  a[9]);
    LOADJ(16, a[18]);
    LOADJ(4,  a[11]);
    LOADJ(13, a[20]);
    LOADJ(5,  a[7]);
    LOADJ(14, a[16]);
    LOADJ(6,  a[4]);
    LOADJ(15, a[13]);
    LOADJ(10, a[5]);
    LOADJ(19, a[14]);
#undef LOADJ

    float acc[4] = {0.0f, 0.0f, 0.0f, 0.0f};
    PairRun<0, NPAIRS>::run(e, f, b1, b3, acc);
    float thread_sum = addi(addi(acc[0], acc[1]), addi(acc[2], acc[3]));

    // ---- block reduction (3 warps) ----
#pragma unroll
    for (int o = 16; o > 0; o >>= 1)
        thread_sum += __shfl_down_sync(0xffffffffu, thread_sum, o);
    if ((tid & 31) == 0) sRed[tid >> 5] = thread_sum;
    __syncthreads();
    if (tid == 0) {
        float bs = sRed[0] + sRed[1] + sRed[2];
        g_partials[blockIdx.x] = bs;
        __threadfence();
        unsigned int old = atomicAdd(&g_count, 1u);
        sLast = (old == (unsigned int)(nblocks - 1));
    }
    __syncthreads();

    // ---- last block finishes the global reduction ----
    if (sLast) {
        __threadfence();
        float v = 0.0f;
        for (int i = tid; i < nblocks; i += THREADS) v += g_partials[i];
#pragma unroll
        for (int o = 16; o > 0; o >>= 1)
            v += __shfl_down_sync(0xffffffffu, v, o);
        if ((tid & 31) == 0) sRed[tid >> 5] = v;
        __syncthreads();
        if (tid == 0) {
            out[0] = (sRed[0] + sRed[1] + sRed[2]) * invB;
            g_count = 0;   // deterministic across graph replays
        }
    }
}

extern "C" void kernel_launch(void* const* d_in, const int* in_sizes, int n_in,
                              void* d_out, int out_size) {
    const float* gin = (const float*)d_in[0];   // input  [B, 63]
    const float* gtg = (const float*)d_in[1];   // target [B, 63]
    float* out = (float*)d_out;                 // [1] float32

    const int B = in_sizes[0] / (NJ * 3);
    int nblocks = (B + SPB - 1) / SPB;
    if (nblocks > MAXBLOCKS) nblocks = MAXBLOCKS;  // B=65536 -> 2048, safe

    comploss_kernel<<<nblocks, THREADS>>>(gin, gtg, out, B, 1.0f / (float)B, nblocks);
}

// round 17
// speedup vs baseline: 1.0329x; 1.0329x over previous
#include <cuda_runtime.h>
#include <cstdint>

// ---------------------------------------------------------------------------
// CompositionalLoss via tree prefix sums.
//   a[j] = a[par(j)] + b[j]   (a[root]=0)
//   e[j] = a[j] - t[j],  f[j] = e[j] - b[j]
//   delta(u,v) = e[u] - f[v] - b[lca];  lca==v -> e[u]-e[v]; lca==u -> f[u]-f[v]
//   Only branching nodes are Hip(3) and Chest(1) -> cross LCA is 1 or 3.
// Instruction diet (1 SASS op each, B300-measured):
//   sub:  fma(b, -1.0f, a)        -> FFMA-imm, rt_SMSP=1
//   acc:  fma(|d|, 1.0f, acc)     -> FFMA-imm with |src| modifier, rt_SMSP=1
// Phase overlap: each 192-thread block = TWO autonomous 3-warp groups.
//   Group g fills ONLY its 32 samples via its own cp.async, waits its own
//   group, then syncs on a NAMED barrier (96 threads). Group 0 computes while
//   group 1's fill is still streaming -> DRAM overlap instead of lockstep.
// ---------------------------------------------------------------------------

#define NJ 21
#define NPAIRS 210
#define SPB 64
#define THREADS 192
#define MAXBLOCKS 4096
#define TILE_FLOATS (SPB * 63)          // 4032 per array
#define GROUP_F4 504                    // float4s per group per array (2016 floats)

__device__ float g_partials[MAXBLOCKS];
__device__ unsigned int g_count = 0;    // self-resets each launch (graph-safe)

// Kinematic tree (JOINTS alphabetical): parent index per joint.
__host__ __device__ constexpr int par(int j) {
    switch (j) {
        case 0:  return 3;   case 1:  return 0;   case 2:  return 12;
        case 3:  return 3;   case 4:  return 11;  case 5:  return 7;
        case 6:  return 4;   case 7:  return 9;   case 8:  return 1;
        case 9:  return 3;   case 10: return 5;   case 11: return 8;
        case 12: return 1;   case 13: return 20;  case 14: return 16;
        case 15: return 13;  case 16: return 18;  case 17: return 1;
        case 18: return 3;   case 19: return 14;  default: return 17;
    }
}
__host__ __device__ constexpr int depthf(int j) {
    int d = 0;
    while (par(j) != j) { j = par(j); ++d; }
    return d;
}
__host__ __device__ constexpr int lcaf(int u, int v) {
    int du = depthf(u), dv = depthf(v);
    while (du > dv) { u = par(u); --du; }
    while (dv > du) { v = par(v); --dv; }
    while (u != v) { u = par(u); v = par(v); }
    return u;
}
// Pair enumeration sorted by v (CSE of per-v group terms, short live ranges).
__host__ __device__ constexpr int qv(int q) {
    int v = 1;
    while (v * (v + 1) / 2 <= q) ++v;
    return v;
}
__host__ __device__ constexpr int qu(int q) {
    int v = qv(q);
    return q - v * (v - 1) / 2;
}

// ---- 1-instruction primitives ----
__device__ __forceinline__ float addi(float a, float b) {   // FFMA-imm rt1
    return __fmaf_rn(a, 1.0f, b);
}
__device__ __forceinline__ float subi(float a, float b) {   // FFMA-imm rt1
    return __fmaf_rn(b, -1.0f, a);
}
__device__ __forceinline__ float acc_abs(float acc, float d) {
    // FFMA Racc, |Rd|, 1.0, Racc  -- abs folds into the source modifier
    return __fmaf_rn(fabsf(d), 1.0f, acc);
}

// Fully-unrolled pair accumulation with compile-time indices; 4 acc chains.
template <int P, int N>
struct PairRun {
    static __device__ __forceinline__ void run(const float (&e)[NJ], const float (&f)[NJ],
                                               float b1, float b3, float (&acc)[4]) {
        PairRun<P, N / 2>::run(e, f, b1, b3, acc);
        PairRun<P + N / 2, N - N / 2>::run(e, f, b1, b3, acc);
    }
};
template <int P>
struct PairRun<P, 1> {
    static __device__ __forceinline__ void run(const float (&e)[NJ], const float (&f)[NJ],
                                               float b1, float b3, float (&acc)[4]) {
        constexpr int u = qu(P);
        constexpr int v = qv(P);
        constexpr int w = lcaf(u, v);
        static_assert(w == u || w == v || w == 1 || w == 3, "unexpected LCA");
        float d;
        if constexpr (w == v)       d = subi(e[u], e[v]);
        else if constexpr (w == u)  d = subi(f[u], f[v]);
        else if constexpr (w == 1)  d = subi(e[u], addi(f[v], b1));  // CSE per v
        else                        d = subi(e[u], addi(f[v], b3));  // CSE per v
        acc[P & 3] = acc_abs(acc[P & 3], d);
    }
};

__device__ __forceinline__ uint32_t smem_u32(const void* p) {
    return (uint32_t)__cvta_generic_to_shared(p);
}
__device__ __forceinline__ void cp_async16(uint32_t dst, const void* src) {
    asm volatile("cp.async.cg.shared.global [%0], [%1], 16;" :: "r"(dst), "l"(src));
}

__global__ __launch_bounds__(THREADS, 6)
void comploss_kernel(const float* __restrict__ gin, const float* __restrict__ gtg,
                     float* __restrict__ out, int B, float invB, int nblocks) {
    __shared__ __align__(16) float sIn[TILE_FLOATS];
    __shared__ __align__(16) float sTg[TILE_FLOATS];
    __shared__ float sRed[THREADS / 32];
    __shared__ bool sLast;

    const int tid  = threadIdx.x;
    const int g    = tid >> 6 >= 2 ? 1 : (tid >= 96 ? 1 : 0);  // see below
    // group: warps 0-2 -> g=0, warps 3-5 -> g=1
    const int grp  = tid / 96;           // 0 or 1
    const int gtid = tid - grp * 96;     // 0..95 within group
    (void)g;

    const long long s0 = (long long)blockIdx.x * SPB;
    int nsamp = B - (int)s0;
    if (nsamp > SPB) nsamp = SPB;

    // ---- fill ----
    if (nsamp == SPB) {
        // Each 3-warp group fills ONLY its own 32 samples and syncs on a
        // named barrier: group 0 can compute while group 1's data streams in.
        const float4* gi = reinterpret_cast<const float4*>(gin + s0 * 63);
        const float4* gt = reinterpret_cast<const float4*>(gtg + s0 * 63);
        const uint32_t si = smem_u32(sIn);
        const uint32_t st = smem_u32(sTg);
        for (int i = gtid; i < GROUP_F4; i += 96) {
            const int idx = grp * GROUP_F4 + i;
            cp_async16(si + idx * 16, gi + idx);
            cp_async16(st + idx * 16, gt + idx);
        }
        asm volatile("cp.async.commit_group;");
        asm volatile("cp.async.wait_group 0;" ::: "memory");
        // named barrier per group: id 1+grp, 96 threads
        asm volatile("bar.sync %0, 96;" :: "r"(1 + grp) : "memory");
    } else {
        // tail block: zero-pad (zeros contribute exactly 0 to the L1 sum)
        for (int i = tid; i < TILE_FLOATS; i += THREADS) {
            bool ok = i < nsamp * 63;
            sIn[i] = ok ? gin[s0 * 63 + i] : 0.0f;
            sTg[i] = ok ? gtg[s0 * 63 + i] : 0.0f;
        }
        __syncthreads();
    }

    // ---- per-(sample,channel) compute ----
    const int c = (tid >> 5) % 3;              // channel, uniform per warp
    const int s = grp * 32 + (tid & 31);       // sample; stride-63: conflict-free
    const float* bp = sIn + s * 63 + c;
    const float* tp = sTg + s * 63 + c;

    float e[NJ], f[NJ], a[NJ];
    float b1, b3;
    // Streaming loads: b,t consumed at point of use; only e/f/b1/b3 stay live.
#define LOADJ(j, apar)                                    \
    { float bb = bp[3 * (j)]; float tt = tp[3 * (j)];     \
      a[j] = addi(apar, bb);                              \
      e[j] = subi(a[j], tt);                              \
      f[j] = subi(e[j], bb); }

    { float bb = bp[9]; float tt = tp[9];                 // root Hip=3, a=0
      a[3] = 0.0f;
      e[3] = subi(0.0f, tt);
      f[3] = subi(e[3], bb);
      b3 = bb; }
    LOADJ(0,  a[3]);
    { float bb = bp[3]; float tt = tp[3];                 // Chest=1, keep b1
      a[1] = addi(a[0], bb);
      e[1] = subi(a[1], tt);
      f[1] = subi(e[1], bb);
      b1 = bb; }
    LOADJ(8,  a[1]);
    LOADJ(12, a[1]);
    LOADJ(17, a[1]);
    LOADJ(2,  a[12]);
    LOADJ(9,  a[3]);
    LOADJ(18, a[3]);
    LOADJ(11, a[8]);
    LOADJ(20, a[17]);
    LOADJ(7,  a[9]);
    LOADJ(16, a[18]);
    LOADJ(4,  a[11]);
    LOADJ(13, a[20]);
    LOADJ(5,  a[7]);
    LOADJ(14, a[16]);
    LOADJ(6,  a[4]);
    LOADJ(15, a[13]);
    LOADJ(10, a[5]);
    LOADJ(19, a[14]);
#undef LOADJ

    float acc[4] = {0.0f, 0.0f, 0.0f, 0.0f};
    PairRun<0, NPAIRS>::run(e, f, b1, b3, acc);
    float thread_sum = addi(addi(acc[0], acc[1]), addi(acc[2], acc[3]));

    // ---- block reduction ----
#pragma unroll
    for (int o = 16; o > 0; o >>= 1)
        thread_sum += __shfl_down_sync(0xffffffffu, thread_sum, o);
    if ((tid & 31) == 0) sRed[tid >> 5] = thread_sum;
    __syncthreads();
    if (tid == 0) {
        float bs = ((sRed[0] + sRed[1]) + (sRed[2] + sRed[3])) + (sRed[4] + sRed[5]);
        g_partials[blockIdx.x] = bs;
        __threadfence();
        unsigned int old = atomicAdd(&g_count, 1u);
        sLast = (old == (unsigned int)(nblocks - 1));
    }
    __syncthreads();

    // ---- last block finishes the global reduction ----
    if (sLast) {
        __threadfence();
        float v = 0.0f;
        for (int i = tid; i < nblocks; i += THREADS) v += g_partials[i];
#pragma unroll
        for (int o = 16; o > 0; o >>= 1)
            v += __shfl_down_sync(0xffffffffu, v, o);
        if ((tid & 31) == 0) sRed[tid >> 5] = v;
        __syncthreads();
        if (tid == 0) {
            float tot = ((sRed[0] + sRed[1]) + (sRed[2] + sRed[3])) + (sRed[4] + sRed[5]);
            out[0] = tot * invB;
            g_count = 0;   // deterministic across graph replays
        }
    }
}

extern "C" void kernel_launch(void* const* d_in, const int* in_sizes, int n_in,
                              void* d_out, int out_size) {
    const float* gin = (const float*)d_in[0];   // input  [B, 63]
    const float* gtg = (const float*)d_in[1];   // target [B, 63]
    float* out = (float*)d_out;                 // [1] float32

    const int B = in_sizes[0] / (NJ * 3);
    int nblocks = (B + SPB - 1) / SPB;
    if (nblocks > MAXBLOCKS) nblocks = MAXBLOCKS;  // B=65536 -> 1024, safe

    comploss_kernel<<<nblocks, THREADS>>>(gin, gtg, out, B, 1.0f / (float)B, nblocks);
}